// round 2
// baseline (speedup 1.0000x reference)
#include <cuda_runtime.h>
#include <cuda_bf16.h>
#include <cstdint>

// ============================================================================
// SwapTestAttention on GB300
//   Phase 1: simulate 6-qubit circuits (1 warp per (token, role)), produce
//            Q/K statevectors (float2 re,im per dim) and V = <Z_q> table.
//   Phase 2: fused pairwise-fidelity + exp-weighted accumulation
//            out_i = sum_j exp(|<q_i|k_j>|^2) * V_j / sum_j exp(...)
//            (logits in [0,1] -> no max subtraction needed; exact softmax ratio)
//   Phase 3: deterministic combine of 8 key-splits + normalize.
// ============================================================================

#define NTOK 8192
#define NQB  6
#define DIM  64      // 2^6 amplitudes
#define NL   2

#define BM 64        // queries per block
#define BN 128       // keys per smem tile
#define KSPLIT 8
#define KEYS_PER_SPLIT (NTOK / KSPLIT)   // 1024
#define NTILES (KEYS_PER_SPLIT / BN)     // 8
#define RSTRIDE 33   // float4 row stride (pad) for Q/K smem tiles

// Scratch (device globals only; no allocation allowed)
__device__ float4 g_Q[NTOK * 32];            // [token][32] float4 = 64 float2 (re,im)
__device__ float4 g_K[NTOK * 32];
__device__ float  g_V[NTOK * 8];             // 6 used + pad
__device__ float  g_part[KSPLIT][NTOK][8];   // per-split partial (6 acc + denom)

__device__ __forceinline__ float shfl_x(float v, int m) {
    return __shfl_xor_sync(0xffffffffu, v, m);
}

// ---------------------------------------------------------------------------
// Phase 1: one warp simulates one (token, role) circuit.
// Lane l holds amplitudes of flat indices n=l (a0, MSB bit5=0) and n=l+32 (a1).
// Qubit q <-> flat bit (5-q): q=0 is the a0/a1 split, q=1..5 are lane bits 4..0.
// ---------------------------------------------------------------------------
__global__ void __launch_bounds__(256) prep_kernel(
    const float* __restrict__ x,
    const float* __restrict__ pq,
    const float* __restrict__ pk,
    const float* __restrict__ pv)
{
    int gw    = (blockIdx.x * 256 + threadIdx.x) >> 5;
    int lane  = threadIdx.x & 31;
    int token = gw & (NTOK - 1);
    int role  = gw >> 13;                  // 0=Q, 1=K, 2=V
    const float* p = (role == 0) ? pq : (role == 1) ? pk : pv;

    float r0 = (lane == 0) ? 1.f : 0.f, i0 = 0.f, r1 = 0.f, i1 = 0.f;

    auto RY = [&](float th, int q) {
        float s, c; __sincosf(0.5f * th, &s, &c);
        if (q == 0) {
            float nr0 = c*r0 - s*r1, ni0 = c*i0 - s*i1;
            float nr1 = s*r0 + c*r1, ni1 = s*i0 + c*i1;
            r0 = nr0; i0 = ni0; r1 = nr1; i1 = ni1;
        } else {
            int m = 1 << (5 - q);
            float pr0 = shfl_x(r0, m), pi0 = shfl_x(i0, m);
            float pr1 = shfl_x(r1, m), pi1 = shfl_x(i1, m);
            float sg = (lane & m) ? s : -s;   // bit=1: +s*partner ; bit=0: -s*partner
            r0 = fmaf(sg, pr0, c*r0); i0 = fmaf(sg, pi0, c*i0);
            r1 = fmaf(sg, pr1, c*r1); i1 = fmaf(sg, pi1, c*i1);
        }
    };
    auto RZ = [&](float th, int q) {
        float s, c; __sincosf(0.5f * th, &s, &c);
        if (q == 0) {
            // a0: phase e^{-i th/2}; a1: e^{+i th/2}
            float nr0 = r0*c + i0*s, ni0 = i0*c - r0*s;
            float nr1 = r1*c - i1*s, ni1 = i1*c + r1*s;
            r0 = nr0; i0 = ni0; r1 = nr1; i1 = ni1;
        } else {
            int m = 1 << (5 - q);
            float sg = (lane & m) ? s : -s;
            float nr0 = r0*c - i0*sg, ni0 = i0*c + r0*sg;
            float nr1 = r1*c - i1*sg, ni1 = i1*c + r1*sg;
            r0 = nr0; i0 = ni0; r1 = nr1; i1 = ni1;
        }
    };

    // RY angle embedding
    #pragma unroll
    for (int q = 0; q < NQB; q++) RY(x[token * NQB + q], q);

    // PQC layers
    #pragma unroll
    for (int l = 0; l < NL; l++) {
        #pragma unroll
        for (int q = 0; q < NQB; q++) {
            RY(p[(l * NQB + q) * 2 + 0], q);
            RZ(p[(l * NQB + q) * 2 + 1], q);
        }
        // CNOT ring (c, t) = (q, q+1 mod 6)
        // (0,1): control = a1 subspace, target = lane bit 4
        r1 = shfl_x(r1, 16); i1 = shfl_x(i1, 16);
        // (q, q+1), q=1..4: both bits are lane bits
        #pragma unroll
        for (int q = 1; q <= 4; q++) {
            int cm = 1 << (5 - q), tm = 1 << (4 - q);
            float t;
            t = shfl_x(r0, tm); if (lane & cm) r0 = t;
            t = shfl_x(i0, tm); if (lane & cm) i0 = t;
            t = shfl_x(r1, tm); if (lane & cm) r1 = t;
            t = shfl_x(i1, tm); if (lane & cm) i1 = t;
        }
        // (5,0): control = lane bit 0, target = a0/a1 swap
        if (lane & 1) { float t = r0; r0 = r1; r1 = t; t = i0; i0 = i1; i1 = t; }
    }

    if (role < 2) {
        float2* buf = (role == 0) ? (float2*)g_Q : (float2*)g_K;
        buf[token * DIM + lane]      = make_float2(r0, i0);
        buf[token * DIM + 32 + lane] = make_float2(r1, i1);
    } else {
        // V_q = sum_n |amp_n|^2 * (1 - 2*bit_q(n))
        float p0 = r0*r0 + i0*i0;   // index n = lane      (bit5 = 0)
        float p1 = r1*r1 + i1*i1;   // index n = lane + 32 (bit5 = 1)
        float v[6];
        v[0] = p0 - p1;
        #pragma unroll
        for (int q = 1; q < 6; q++) {
            float sgn = ((lane >> (5 - q)) & 1) ? -1.f : 1.f;
            v[q] = sgn * (p0 + p1);
        }
        #pragma unroll
        for (int off = 16; off >= 1; off >>= 1) {
            #pragma unroll
            for (int q = 0; q < 6; q++) v[q] += __shfl_down_sync(0xffffffffu, v[q], off);
        }
        if (lane == 0) {
            #pragma unroll
            for (int q = 0; q < 6; q++) g_V[token * 8 + q] = v[q];
            g_V[token * 8 + 6] = 0.f;
            g_V[token * 8 + 7] = 0.f;
        }
    }
}

// ---------------------------------------------------------------------------
// Phase 2: fused fidelity + exp-weighted V accumulation.
// Block = (query tile qt of 64, key split ks of 1024 keys).
// Thread (mrow = tid>>4, ncol = tid&15) owns 4 queries x 8 keys per tile.
// per pair, per complex dim d: re += qr*kr + qi*ki ; im += qi*kr - qr*ki (4 FMA)
// ---------------------------------------------------------------------------
__global__ void __launch_bounds__(256, 1) attn_kernel()
{
    extern __shared__ float4 smem4[];
    float4* Qs = smem4;                          // BM * RSTRIDE
    float4* Ks = smem4 + BM * RSTRIDE;           // BN * RSTRIDE
    float*  Vs = (float*)(smem4 + (BM + BN) * RSTRIDE);  // BN * 9

    int tid  = threadIdx.x;
    int qt   = blockIdx.x;     // 0..127
    int ks   = blockIdx.y;     // 0..7
    int ncol = tid & 15;
    int mrow = tid >> 4;
    int q0   = qt * BM;

    // load Q tile (64 rows x 32 float4), conflict-free padded rows
    const float4* Qg = g_Q + (size_t)q0 * 32;
    for (int idx = tid; idx < BM * 32; idx += 256) {
        int r = idx >> 5, c = idx & 31;
        Qs[r * RSTRIDE + c] = Qg[idx];
    }

    float den[4] = {0.f, 0.f, 0.f, 0.f};
    float acc[4][6];
    #pragma unroll
    for (int m = 0; m < 4; m++)
        #pragma unroll
        for (int c = 0; c < 6; c++) acc[m][c] = 0.f;

    for (int kt = 0; kt < NTILES; kt++) {
        int key0 = ks * KEYS_PER_SPLIT + kt * BN;
        __syncthreads();   // previous tile fully consumed
        const float4* Kg = g_K + (size_t)key0 * 32;
        for (int idx = tid; idx < BN * 32; idx += 256) {
            int r = idx >> 5, c = idx & 31;
            Ks[r * RSTRIDE + c] = Kg[idx];
        }
        const float* Vg = g_V + (size_t)key0 * 8;
        for (int idx = tid; idx < BN * 8; idx += 256) {
            int r = idx >> 3, c = idx & 7;
            Vs[r * 9 + c] = Vg[idx];
        }
        __syncthreads();

        float re[4][8], im[4][8];
        #pragma unroll
        for (int m = 0; m < 4; m++)
            #pragma unroll
            for (int n = 0; n < 8; n++) { re[m][n] = 0.f; im[m][n] = 0.f; }

        #pragma unroll 2
        for (int d = 0; d < 32; d++) {   // 32 float4 = 64 complex dims
            float4 qv[4], kv[8];
            #pragma unroll
            for (int m = 0; m < 4; m++) qv[m] = Qs[(mrow * 4 + m) * RSTRIDE + d];
            #pragma unroll
            for (int n = 0; n < 8; n++) kv[n] = Ks[(n * 16 + ncol) * RSTRIDE + d];
            #pragma unroll
            for (int m = 0; m < 4; m++) {
                #pragma unroll
                for (int n = 0; n < 8; n++) {
                    re[m][n] = fmaf(qv[m].x, kv[n].x, re[m][n]);
                    re[m][n] = fmaf(qv[m].y, kv[n].y, re[m][n]);
                    re[m][n] = fmaf(qv[m].z, kv[n].z, re[m][n]);
                    re[m][n] = fmaf(qv[m].w, kv[n].w, re[m][n]);
                    im[m][n] = fmaf(qv[m].y,  kv[n].x, im[m][n]);
                    im[m][n] = fmaf(-qv[m].x, kv[n].y, im[m][n]);
                    im[m][n] = fmaf(qv[m].w,  kv[n].z, im[m][n]);
                    im[m][n] = fmaf(-qv[m].z, kv[n].w, im[m][n]);
                }
            }
        }

        // epilogue: l = re^2 + im^2 in [0,1]; accumulate exp(l)*V and exp(l)
        #pragma unroll
        for (int n = 0; n < 8; n++) {
            float vv[6];
            #pragma unroll
            for (int c = 0; c < 6; c++) vv[c] = Vs[(n * 16 + ncol) * 9 + c];
            #pragma unroll
            for (int m = 0; m < 4; m++) {
                float l = fmaf(re[m][n], re[m][n], im[m][n] * im[m][n]);
                float w = __expf(l);
                den[m] += w;
                #pragma unroll
                for (int c = 0; c < 6; c++) acc[m][c] = fmaf(w, vv[c], acc[m][c]);
            }
        }
    }

    // reduce partials across the 16 ncol lanes sharing each query
    #pragma unroll
    for (int off = 8; off >= 1; off >>= 1) {
        #pragma unroll
        for (int m = 0; m < 4; m++) {
            den[m] += __shfl_xor_sync(0xffffffffu, den[m], off);
            #pragma unroll
            for (int c = 0; c < 6; c++)
                acc[m][c] += __shfl_xor_sync(0xffffffffu, acc[m][c], off);
        }
    }
    if (ncol == 0) {
        #pragma unroll
        for (int m = 0; m < 4; m++) {
            int qi = q0 + mrow * 4 + m;
            #pragma unroll
            for (int c = 0; c < 6; c++) g_part[ks][qi][c] = acc[m][c];
            g_part[ks][qi][6] = den[m];
        }
    }
}

// ---------------------------------------------------------------------------
// Phase 3: deterministic combine of the 8 key-splits + normalize.
// ---------------------------------------------------------------------------
__global__ void __launch_bounds__(256) finalize_kernel(float* __restrict__ out)
{
    int i = blockIdx.x * 256 + threadIdx.x;
    if (i >= NTOK) return;
    float den = 0.f;
    float num[6] = {0.f, 0.f, 0.f, 0.f, 0.f, 0.f};
    #pragma unroll
    for (int ks = 0; ks < KSPLIT; ks++) {
        den += g_part[ks][i][6];
        #pragma unroll
        for (int c = 0; c < 6; c++) num[c] += g_part[ks][i][c];
    }
    float inv = 1.f / den;
    #pragma unroll
    for (int c = 0; c < 6; c++) out[i * 6 + c] = num[c] * inv;
}

// ---------------------------------------------------------------------------
extern "C" void kernel_launch(void* const* d_in, const int* in_sizes, int n_in,
                              void* d_out, int out_size)
{
    const float* x  = (const float*)d_in[0];  // (8192, 6)
    const float* pq = (const float*)d_in[1];  // (2, 6, 2)
    const float* pk = (const float*)d_in[2];
    const float* pv = (const float*)d_in[3];
    float* out = (float*)d_out;               // (8192, 6) f32

    prep_kernel<<<(NTOK * 3) / 8, 256>>>(x, pq, pk, pv);

    size_t smem = (size_t)(BM + BN) * RSTRIDE * sizeof(float4) + (size_t)BN * 9 * sizeof(float);
    cudaFuncSetAttribute(attn_kernel, cudaFuncAttributeMaxDynamicSharedMemorySize, (int)smem);
    attn_kernel<<<dim3(NTOK / BM, KSPLIT), 256, smem>>>();

    finalize_kernel<<<NTOK / 256, 256>>>(out);
}